// round 1
// baseline (speedup 1.0000x reference)
#include <cuda_runtime.h>

#define NNODES 100000
#define EEDGES 1600000
#define HDIM   128

// Scratch (device globals: no allocation allowed in kernel_launch)
__device__ float g_h[(size_t)NNODES * HDIM];     // 51.2 MB: post-GEMM features
__device__ float g_agg[(size_t)NNODES * HDIM];   // 51.2 MB: aggregated features
__device__ float g_dinv[NNODES];                 // deg^{-1/2}

// ---------------------------------------------------------------------------
// Degree computation: deg = indegree(dst) + 1 (self loop), then dinv = rsqrt
// ---------------------------------------------------------------------------
__global__ void deg_init(float* __restrict__ deg) {
    int i = blockIdx.x * blockDim.x + threadIdx.x;
    if (i < NNODES) deg[i] = 1.0f;   // self-loop contribution
}

__global__ void deg_count(const int* __restrict__ dst, float* __restrict__ deg) {
    int e = blockIdx.x * blockDim.x + threadIdx.x;
    if (e < EEDGES) atomicAdd(&deg[dst[e]], 1.0f);
}

__global__ void deg_finalize(float* __restrict__ deg) {
    int i = blockIdx.x * blockDim.x + threadIdx.x;
    if (i < NNODES) deg[i] = rsqrtf(deg[i]);   // deg >= 1 always
}

// ---------------------------------------------------------------------------
// GEMM: C[M,128] = f(A)[M,128] @ W[128,128]
//   f(a)[m,k] = relu(a[m,k] + bin[k])  if bin != nullptr (fused prev-layer
//   bias + ReLU), else identity.
// BM=64, BN=128, BK=32, 256 threads, 4x8 micro-tile per thread.
// ---------------------------------------------------------------------------
__global__ __launch_bounds__(256)
void gemm_act(const float* __restrict__ A, const float* __restrict__ W,
              const float* __restrict__ bin, float* __restrict__ C) {
    __shared__ float As[32][68];    // [k][m], pad: row stride 272B (16B-aligned)
    __shared__ float Bs[32][132];   // [k][n], pad: row stride 528B (16B-aligned)

    const int bm  = blockIdx.x * 64;
    const int tid = threadIdx.x;
    const int tx  = tid & 15;       // 16 col-groups of 8
    const int ty  = tid >> 4;       // 16 row-groups of 4

    float acc[4][8];
#pragma unroll
    for (int i = 0; i < 4; i++)
#pragma unroll
        for (int j = 0; j < 8; j++) acc[i][j] = 0.0f;

    for (int k0 = 0; k0 < 128; k0 += 32) {
        // Load A tile (64 rows x 32 k) with fused bias+ReLU, store transposed.
#pragma unroll
        for (int t = tid; t < 512; t += 256) {
            int r  = t >> 3;        // 0..63
            int c4 = t & 7;         // float4 index in k
            int row = bm + r;
            float4 v = make_float4(0.f, 0.f, 0.f, 0.f);
            if (row < NNODES)
                v = *(const float4*)&A[(size_t)row * 128 + k0 + c4 * 4];
            if (bin) {
                float4 bb = *(const float4*)&bin[k0 + c4 * 4];
                v.x = fmaxf(v.x + bb.x, 0.f);
                v.y = fmaxf(v.y + bb.y, 0.f);
                v.z = fmaxf(v.z + bb.z, 0.f);
                v.w = fmaxf(v.w + bb.w, 0.f);
            }
            As[c4 * 4 + 0][r] = v.x;
            As[c4 * 4 + 1][r] = v.y;
            As[c4 * 4 + 2][r] = v.z;
            As[c4 * 4 + 3][r] = v.w;
        }
        // Load W tile (32 k x 128 n)
#pragma unroll
        for (int t = tid; t < 1024; t += 256) {
            int r  = t >> 5;        // 0..31
            int c4 = t & 31;        // 0..31
            *(float4*)&Bs[r][c4 * 4] =
                *(const float4*)&W[(size_t)(k0 + r) * 128 + c4 * 4];
        }
        __syncthreads();

#pragma unroll
        for (int kk = 0; kk < 32; kk++) {
            float4 a  = *(const float4*)&As[kk][ty * 4];
            float4 b0 = *(const float4*)&Bs[kk][tx * 8];
            float4 b1 = *(const float4*)&Bs[kk][tx * 8 + 4];
            float av[4] = {a.x, a.y, a.z, a.w};
            float bv[8] = {b0.x, b0.y, b0.z, b0.w, b1.x, b1.y, b1.z, b1.w};
#pragma unroll
            for (int i = 0; i < 4; i++)
#pragma unroll
                for (int j = 0; j < 8; j++)
                    acc[i][j] += av[i] * bv[j];
        }
        __syncthreads();
    }

#pragma unroll
    for (int i = 0; i < 4; i++) {
        int row = bm + ty * 4 + i;
        if (row < NNODES) {
            *(float4*)&C[(size_t)row * 128 + tx * 8] =
                make_float4(acc[i][0], acc[i][1], acc[i][2], acc[i][3]);
            *(float4*)&C[(size_t)row * 128 + tx * 8 + 4] =
                make_float4(acc[i][4], acc[i][5], acc[i][6], acc[i][7]);
        }
    }
}

// ---------------------------------------------------------------------------
// Self-loop init: agg[i,:] = h[i,:] * dinv[i]^2   (also zeroes stale agg)
// One thread per float4.
// ---------------------------------------------------------------------------
__global__ void self_init(const float* __restrict__ h,
                          const float* __restrict__ dinv,
                          float* __restrict__ out) {
    int idx = blockIdx.x * blockDim.x + threadIdx.x;   // over NNODES*32
    if (idx >= NNODES * 32) return;
    int node = idx >> 5;
    float s = dinv[node];
    s = s * s;
    float4 v = ((const float4*)h)[idx];
    v.x *= s; v.y *= s; v.z *= s; v.w *= s;
    ((float4*)out)[idx] = v;
}

// ---------------------------------------------------------------------------
// Edge scatter: one warp per edge.
//   agg[dst,:] += h[src,:] * dinv[src] * dinv[dst]
// Each lane owns a float4 (128 floats / 32 lanes). Vector L2 reduction.
// ---------------------------------------------------------------------------
__global__ void edge_scatter(const int* __restrict__ src,
                             const int* __restrict__ dst,
                             const float* __restrict__ h,
                             const float* __restrict__ dinv,
                             float* __restrict__ out) {
    int gw = (int)((blockIdx.x * (unsigned)blockDim.x + threadIdx.x) >> 5);
    if (gw >= EEDGES) return;
    int lane = threadIdx.x & 31;
    int s = __ldg(&src[gw]);
    int d = __ldg(&dst[gw]);
    float norm = __ldg(&dinv[s]) * __ldg(&dinv[d]);
    float4 v = *(const float4*)(h + (size_t)s * HDIM + lane * 4);
    float* op = out + (size_t)d * HDIM + lane * 4;
    asm volatile("red.global.add.v4.f32 [%0], {%1,%2,%3,%4};"
                 :: "l"(op), "f"(v.x * norm), "f"(v.y * norm),
                    "f"(v.z * norm), "f"(v.w * norm)
                 : "memory");
}

// ---------------------------------------------------------------------------
// Final epilogue: out = relu(agg + b2)
// ---------------------------------------------------------------------------
__global__ void bias_relu_out(const float* __restrict__ agg,
                              const float* __restrict__ b,
                              float* __restrict__ out) {
    int idx = blockIdx.x * blockDim.x + threadIdx.x;   // over NNODES*32
    if (idx >= NNODES * 32) return;
    int c4 = idx & 31;
    float4 bb = *(const float4*)&b[c4 * 4];
    float4 v = ((const float4*)agg)[idx];
    v.x = fmaxf(v.x + bb.x, 0.f);
    v.y = fmaxf(v.y + bb.y, 0.f);
    v.z = fmaxf(v.z + bb.z, 0.f);
    v.w = fmaxf(v.w + bb.w, 0.f);
    ((float4*)out)[idx] = v;
}

// ---------------------------------------------------------------------------
extern "C" void kernel_launch(void* const* d_in, const int* in_sizes, int n_in,
                              void* d_out, int out_size) {
    const float* x  = (const float*)d_in[0];
    const int*   ei = (const int*)d_in[1];
    const float* W0 = (const float*)d_in[2];
    const float* b0 = (const float*)d_in[3];
    const float* W1 = (const float*)d_in[4];
    const float* b1 = (const float*)d_in[5];
    const float* W2 = (const float*)d_in[6];
    const float* b2 = (const float*)d_in[7];
    const int* src = ei;            // edge_index[0]
    const int* dst = ei + EEDGES;   // edge_index[1]

    float *h, *agg, *dinv;
    cudaGetSymbolAddress((void**)&h,    g_h);
    cudaGetSymbolAddress((void**)&agg,  g_agg);
    cudaGetSymbolAddress((void**)&dinv, g_dinv);

    // Degree / normalization
    deg_init<<<(NNODES + 255) / 256, 256>>>(dinv);
    deg_count<<<(EEDGES + 255) / 256, 256>>>(dst, dinv);
    deg_finalize<<<(NNODES + 255) / 256, 256>>>(dinv);

    const float* Ws[3] = {W0, W1, W2};
    const float* bs[3] = {b0, b1, b2};

    const float* in = x;
    const int gemm_blocks    = (NNODES + 63) / 64;
    const int elem_blocks    = (NNODES * 32 + 255) / 256;
    const int scatter_blocks = (EEDGES + 7) / 8;   // 8 warps per 256-thread block

    for (int l = 0; l < 3; l++) {
        gemm_act<<<gemm_blocks, 256>>>(in, Ws[l], l ? bs[l - 1] : nullptr, h);
        self_init<<<elem_blocks, 256>>>(h, dinv, agg);
        edge_scatter<<<scatter_blocks, 256>>>(src, dst, h, dinv, agg);
        in = agg;
    }

    bias_relu_out<<<elem_blocks, 256>>>(agg, b2, (float*)d_out);
}

// round 2
// speedup vs baseline: 1.7730x; 1.7730x over previous
#include <cuda_runtime.h>

#define NNODES 100000
#define EEDGES 1600000
#define HDIM   128

#define SCAN_BLK 1024
#define SCAN_T   256
#define NSCAN    ((NNODES + SCAN_BLK - 1) / SCAN_BLK)   // 98

// Scratch (device globals: no allocation allowed in kernel_launch)
__device__ float g_h[(size_t)NNODES * HDIM];     // 51.2 MB: post-GEMM (dinv-scaled)
__device__ float g_agg[(size_t)NNODES * HDIM];   // 51.2 MB: aggregated features
__device__ float g_dinv[NNODES];                 // deg^{-1/2}
__device__ int   g_deg[NNODES];                  // in-degree (no self loop)
__device__ int   g_off[NNODES + 1];              // CSR offsets
__device__ int   g_cur[NNODES];                  // fill cursors
__device__ int   g_csr[EEDGES];                  // CSR payload: src node ids
__device__ int   g_bsum[NSCAN];
__device__ int   g_bbase[NSCAN];

// ---------------------------------------------------------------------------
// Degree / CSR build
// ---------------------------------------------------------------------------
__global__ void zero_deg() {
    int i = blockIdx.x * blockDim.x + threadIdx.x;
    if (i < NNODES) g_deg[i] = 0;
}

__global__ void deg_count(const int* __restrict__ dst) {
    int e = blockIdx.x * blockDim.x + threadIdx.x;
    if (e < EEDGES) atomicAdd(&g_deg[dst[e]], 1);
}

__global__ void dinv_kernel() {
    int i = blockIdx.x * blockDim.x + threadIdx.x;
    if (i < NNODES) g_dinv[i] = rsqrtf((float)g_deg[i] + 1.0f);  // +1 self loop
}

// scan1: per-block local exclusive scan of g_deg -> g_off, block totals -> g_bsum
__global__ __launch_bounds__(SCAN_T)
void scan1() {
    __shared__ int sh[SCAN_T];
    int b = blockIdx.x, t = threadIdx.x;
    int base = b * SCAN_BLK + t * 4;
    int v[4];
#pragma unroll
    for (int j = 0; j < 4; j++) {
        int i = base + j;
        v[j] = (i < NNODES) ? g_deg[i] : 0;
    }
    int tot = v[0] + v[1] + v[2] + v[3];
    sh[t] = tot;
    __syncthreads();
    for (int o = 1; o < SCAN_T; o <<= 1) {
        int x = 0;
        if (t >= o) x = sh[t - o];
        __syncthreads();
        if (t >= o) sh[t] += x;
        __syncthreads();
    }
    int run = sh[t] - tot;   // exclusive base for this thread
#pragma unroll
    for (int j = 0; j < 4; j++) {
        int i = base + j;
        if (i < NNODES) g_off[i] = run;
        run += v[j];
    }
    if (t == SCAN_T - 1) g_bsum[b] = sh[t];
}

// scan2: serial exclusive scan of block sums (98 entries)
__global__ void scan2() {
    if (threadIdx.x == 0 && blockIdx.x == 0) {
        int run = 0;
        for (int i = 0; i < NSCAN; i++) {
            g_bbase[i] = run;
            run += g_bsum[i];
        }
        g_off[NNODES] = run;   // == EEDGES
    }
}

// scan3: add block bases; init fill cursors
__global__ void scan3() {
    int i = blockIdx.x * blockDim.x + threadIdx.x;
    if (i < NNODES) {
        int v = g_off[i] + g_bbase[i / SCAN_BLK];
        g_off[i] = v;
        g_cur[i] = v;
    }
}

__global__ void csr_fill(const int* __restrict__ src, const int* __restrict__ dst) {
    int e = blockIdx.x * blockDim.x + threadIdx.x;
    if (e < EEDGES) {
        int d = dst[e];
        int slot = atomicAdd(&g_cur[d], 1);
        g_csr[slot] = src[e];
    }
}

// ---------------------------------------------------------------------------
// GEMM: C[M,128] = dinv[row] * ( f(A)[M,128] @ W[128,128] )
//   f(a)[m,k] = relu(a[m,k] + bin[k])  if bin != nullptr, else identity.
// BM=64, BN=128, BK=32, 256 threads, 4x8 micro-tile per thread.
// ---------------------------------------------------------------------------
__global__ __launch_bounds__(256)
void gemm_act(const float* __restrict__ A, const float* __restrict__ W,
              const float* __restrict__ bin, const float* __restrict__ dinv,
              float* __restrict__ C) {
    __shared__ float As[32][68];
    __shared__ float Bs[32][132];

    const int bm  = blockIdx.x * 64;
    const int tid = threadIdx.x;
    const int tx  = tid & 15;
    const int ty  = tid >> 4;

    float acc[4][8];
#pragma unroll
    for (int i = 0; i < 4; i++)
#pragma unroll
        for (int j = 0; j < 8; j++) acc[i][j] = 0.0f;

    for (int k0 = 0; k0 < 128; k0 += 32) {
#pragma unroll
        for (int t = tid; t < 512; t += 256) {
            int r  = t >> 3;
            int c4 = t & 7;
            int row = bm + r;
            float4 v = make_float4(0.f, 0.f, 0.f, 0.f);
            if (row < NNODES)
                v = *(const float4*)&A[(size_t)row * 128 + k0 + c4 * 4];
            if (bin) {
                float4 bb = *(const float4*)&bin[k0 + c4 * 4];
                v.x = fmaxf(v.x + bb.x, 0.f);
                v.y = fmaxf(v.y + bb.y, 0.f);
                v.z = fmaxf(v.z + bb.z, 0.f);
                v.w = fmaxf(v.w + bb.w, 0.f);
            }
            As[c4 * 4 + 0][r] = v.x;
            As[c4 * 4 + 1][r] = v.y;
            As[c4 * 4 + 2][r] = v.z;
            As[c4 * 4 + 3][r] = v.w;
        }
#pragma unroll
        for (int t = tid; t < 1024; t += 256) {
            int r  = t >> 5;
            int c4 = t & 31;
            *(float4*)&Bs[r][c4 * 4] =
                *(const float4*)&W[(size_t)(k0 + r) * 128 + c4 * 4];
        }
        __syncthreads();

#pragma unroll
        for (int kk = 0; kk < 32; kk++) {
            float4 a  = *(const float4*)&As[kk][ty * 4];
            float4 b0 = *(const float4*)&Bs[kk][tx * 8];
            float4 b1 = *(const float4*)&Bs[kk][tx * 8 + 4];
            float av[4] = {a.x, a.y, a.z, a.w};
            float bv[8] = {b0.x, b0.y, b0.z, b0.w, b1.x, b1.y, b1.z, b1.w};
#pragma unroll
            for (int i = 0; i < 4; i++)
#pragma unroll
                for (int j = 0; j < 8; j++)
                    acc[i][j] += av[i] * bv[j];
        }
        __syncthreads();
    }

#pragma unroll
    for (int i = 0; i < 4; i++) {
        int row = bm + ty * 4 + i;
        if (row < NNODES) {
            float s = dinv[row];
            *(float4*)&C[(size_t)row * 128 + tx * 8] =
                make_float4(acc[i][0] * s, acc[i][1] * s, acc[i][2] * s, acc[i][3] * s);
            *(float4*)&C[(size_t)row * 128 + tx * 8 + 4] =
                make_float4(acc[i][4] * s, acc[i][5] * s, acc[i][6] * s, acc[i][7] * s);
        }
    }
}

// ---------------------------------------------------------------------------
// Gather: one warp per node d.
//   agg[d,:] = dinv[d] * ( hs[d,:] + sum_{s in in(d)} hs[s,:] )
// Each lane owns a float4 (128 floats / 32 lanes).
// ---------------------------------------------------------------------------
__global__ __launch_bounds__(256)
void gather(const float* __restrict__ hs, float* __restrict__ out) {
    int w = (int)((blockIdx.x * (unsigned)blockDim.x + threadIdx.x) >> 5);
    if (w >= NNODES) return;
    int lane = threadIdx.x & 31;
    const float4* hp = (const float4*)hs;

    int e    = g_off[w];
    int eend = g_off[w + 1];

    float4 acc = __ldg(&hp[w * 32 + lane]);   // self loop (hs already dinv-scaled)

    for (; e + 4 <= eend; e += 4) {
        int s0 = __ldg(&g_csr[e + 0]);
        int s1 = __ldg(&g_csr[e + 1]);
        int s2 = __ldg(&g_csr[e + 2]);
        int s3 = __ldg(&g_csr[e + 3]);
        float4 v0 = __ldg(&hp[s0 * 32 + lane]);
        float4 v1 = __ldg(&hp[s1 * 32 + lane]);
        float4 v2 = __ldg(&hp[s2 * 32 + lane]);
        float4 v3 = __ldg(&hp[s3 * 32 + lane]);
        acc.x += (v0.x + v1.x) + (v2.x + v3.x);
        acc.y += (v0.y + v1.y) + (v2.y + v3.y);
        acc.z += (v0.z + v1.z) + (v2.z + v3.z);
        acc.w += (v0.w + v1.w) + (v2.w + v3.w);
    }
    for (; e < eend; e++) {
        int s = __ldg(&g_csr[e]);
        float4 v = __ldg(&hp[s * 32 + lane]);
        acc.x += v.x; acc.y += v.y; acc.z += v.z; acc.w += v.w;
    }

    float sc = __ldg(&g_dinv[w]);
    acc.x *= sc; acc.y *= sc; acc.z *= sc; acc.w *= sc;
    ((float4*)out)[w * 32 + lane] = acc;
}

// ---------------------------------------------------------------------------
// Final epilogue: out = relu(agg + b2)
// ---------------------------------------------------------------------------
__global__ void bias_relu_out(const float* __restrict__ agg,
                              const float* __restrict__ b,
                              float* __restrict__ out) {
    int idx = blockIdx.x * blockDim.x + threadIdx.x;
    if (idx >= NNODES * 32) return;
    int c4 = idx & 31;
    float4 bb = *(const float4*)&b[c4 * 4];
    float4 v = ((const float4*)agg)[idx];
    v.x = fmaxf(v.x + bb.x, 0.f);
    v.y = fmaxf(v.y + bb.y, 0.f);
    v.z = fmaxf(v.z + bb.z, 0.f);
    v.w = fmaxf(v.w + bb.w, 0.f);
    ((float4*)out)[idx] = v;
}

// ---------------------------------------------------------------------------
extern "C" void kernel_launch(void* const* d_in, const int* in_sizes, int n_in,
                              void* d_out, int out_size) {
    const float* x  = (const float*)d_in[0];
    const int*   ei = (const int*)d_in[1];
    const float* W0 = (const float*)d_in[2];
    const float* b0 = (const float*)d_in[3];
    const float* W1 = (const float*)d_in[4];
    const float* b1 = (const float*)d_in[5];
    const float* W2 = (const float*)d_in[6];
    const float* b2 = (const float*)d_in[7];
    const int* src = ei;            // edge_index[0]
    const int* dst = ei + EEDGES;   // edge_index[1]

    float *h, *agg, *dinv;
    cudaGetSymbolAddress((void**)&h,    g_h);
    cudaGetSymbolAddress((void**)&agg,  g_agg);
    cudaGetSymbolAddress((void**)&dinv, g_dinv);

    // Degree + CSR build
    zero_deg<<<(NNODES + 255) / 256, 256>>>();
    deg_count<<<(EEDGES + 255) / 256, 256>>>(dst);
    dinv_kernel<<<(NNODES + 255) / 256, 256>>>();
    scan1<<<NSCAN, SCAN_T>>>();
    scan2<<<1, 32>>>();
    scan3<<<(NNODES + 255) / 256, 256>>>();
    csr_fill<<<(EEDGES + 255) / 256, 256>>>(src, dst);

    const float* Ws[3] = {W0, W1, W2};
    const float* bs[3] = {b0, b1, b2};

    const float* in = x;
    const int gemm_blocks   = (NNODES + 63) / 64;
    const int elem_blocks   = (NNODES * 32 + 255) / 256;
    const int gather_blocks = (NNODES + 7) / 8;   // 8 warps / 256-thread block

    for (int l = 0; l < 3; l++) {
        gemm_act<<<gemm_blocks, 256>>>(in, Ws[l], l ? bs[l - 1] : nullptr, dinv, h);
        gather<<<gather_blocks, 256>>>(h, agg);
        in = agg;
    }

    bias_relu_out<<<elem_blocks, 256>>>(agg, b2, (float*)d_out);
}

// round 4
// speedup vs baseline: 2.9830x; 1.6824x over previous
#include <cuda_runtime.h>
#include <cuda_bf16.h>
#include <cstdint>

#define NNODES 100000
#define EEDGES 1600000
#define HDIM   128

#define SCAN_BLK 1024
#define SCAN_T   256
#define NSCAN    ((NNODES + SCAN_BLK - 1) / SCAN_BLK)   // 98

#define MTILE   128
#define NTILES  ((NNODES + MTILE - 1) / MTILE)          // 782
#define PADH    136                                      // halves per padded row (272 B)
#define TILEB   (128 * PADH * 2)                         // 34816 B per bf16 tile
#define SMEM_DYN (4 * TILEB)                             // A_hi, A_lo, W_hi, W_lo

// ---------------------------------------------------------------------------
// Scratch (device globals)
// ---------------------------------------------------------------------------
__device__ float g_h[(size_t)NNODES * HDIM];
__device__ float g_agg[(size_t)NNODES * HDIM];
__device__ float g_dinv[NNODES];
__device__ int   g_deg[NNODES];
__device__ int   g_off[NNODES + 1];
__device__ int   g_cur[NNODES];
__device__ int   g_csr[EEDGES];
__device__ int   g_bsum[NSCAN];
__device__ int   g_bbase[NSCAN];
__device__ __nv_bfloat16 g_Wt[3][2][128 * 128];   // k-major W, hi/lo split

// ---------------------------------------------------------------------------
__device__ __forceinline__ uint32_t smem_u32(const void* p) {
    uint32_t a;
    asm("{ .reg .u64 t; cvta.to.shared.u64 t, %1; cvt.u32.u64 %0, t; }"
        : "=r"(a) : "l"(p));
    return a;
}

#define LDSM_X4(r, a) \
    asm volatile("ldmatrix.sync.aligned.m8n8.x4.shared.b16 {%0,%1,%2,%3}, [%4];" \
                 : "=r"((r)[0]), "=r"((r)[1]), "=r"((r)[2]), "=r"((r)[3]) : "r"(a))
#define LDSM_X4T(r, a) \
    asm volatile("ldmatrix.sync.aligned.m8n8.x4.trans.shared.b16 {%0,%1,%2,%3}, [%4];" \
                 : "=r"((r)[0]), "=r"((r)[1]), "=r"((r)[2]), "=r"((r)[3]) : "r"(a))
#define MMA_BF16(c, a, b0, b1) \
    asm volatile("mma.sync.aligned.m16n8k16.row.col.f32.bf16.bf16.f32 " \
                 "{%0,%1,%2,%3}, {%4,%5,%6,%7}, {%8,%9}, {%0,%1,%2,%3};" \
                 : "+f"((c)[0]), "+f"((c)[1]), "+f"((c)[2]), "+f"((c)[3]) \
                 : "r"((a)[0]), "r"((a)[1]), "r"((a)[2]), "r"((a)[3]), \
                   "r"(b0), "r"(b1))

// ---------------------------------------------------------------------------
// Degree / CSR build
// ---------------------------------------------------------------------------
__global__ void zero_deg() {
    int i = blockIdx.x * blockDim.x + threadIdx.x;
    if (i < NNODES) g_deg[i] = 0;
}
__global__ void deg_count(const int* __restrict__ dst) {
    int e = blockIdx.x * blockDim.x + threadIdx.x;
    if (e < EEDGES) atomicAdd(&g_deg[dst[e]], 1);
}
__global__ void dinv_kernel() {
    int i = blockIdx.x * blockDim.x + threadIdx.x;
    if (i < NNODES) g_dinv[i] = rsqrtf((float)g_deg[i] + 1.0f);
}
__global__ __launch_bounds__(SCAN_T)
void scan1() {
    __shared__ int sh[SCAN_T];
    int b = blockIdx.x, t = threadIdx.x;
    int base = b * SCAN_BLK + t * 4;
    int v[4];
#pragma unroll
    for (int j = 0; j < 4; j++) {
        int i = base + j;
        v[j] = (i < NNODES) ? g_deg[i] : 0;
    }
    int tot = v[0] + v[1] + v[2] + v[3];
    sh[t] = tot;
    __syncthreads();
    for (int o = 1; o < SCAN_T; o <<= 1) {
        int x = 0;
        if (t >= o) x = sh[t - o];
        __syncthreads();
        if (t >= o) sh[t] += x;
        __syncthreads();
    }
    int run = sh[t] - tot;
#pragma unroll
    for (int j = 0; j < 4; j++) {
        int i = base + j;
        if (i < NNODES) g_off[i] = run;
        run += v[j];
    }
    if (t == SCAN_T - 1) g_bsum[b] = sh[t];
}
__global__ void scan2() {
    if (threadIdx.x == 0 && blockIdx.x == 0) {
        int run = 0;
        for (int i = 0; i < NSCAN; i++) { g_bbase[i] = run; run += g_bsum[i]; }
        g_off[NNODES] = run;
    }
}
__global__ void scan3() {
    int i = blockIdx.x * blockDim.x + threadIdx.x;
    if (i < NNODES) {
        int v = g_off[i] + g_bbase[i / SCAN_BLK];
        g_off[i] = v;
        g_cur[i] = v;
    }
}
__global__ void csr_fill(const int* __restrict__ src, const int* __restrict__ dst) {
    int e = blockIdx.x * blockDim.x + threadIdx.x;
    if (e < EEDGES) {
        int d = dst[e];
        int slot = atomicAdd(&g_cur[d], 1);
        g_csr[slot] = src[e];
    }
}

// ---------------------------------------------------------------------------
// Prep: split W (k-major, [k][n]) into bf16 hi/lo.
// ---------------------------------------------------------------------------
__global__ void prep_w(const float* __restrict__ W0, const float* __restrict__ W1,
                       const float* __restrict__ W2) {
    int idx = blockIdx.x * blockDim.x + threadIdx.x;
    if (idx >= 3 * 16384) return;
    int l = idx >> 14;
    int e = idx & 16383;
    const float* W = (l == 0) ? W0 : (l == 1) ? W1 : W2;
    float v = W[e];
    __nv_bfloat16 hi = __float2bfloat16(v);
    __nv_bfloat16 lo = __float2bfloat16(v - __bfloat162float(hi));
    g_Wt[l][0][e] = hi;
    g_Wt[l][1][e] = lo;
}

// ---------------------------------------------------------------------------
// Tensor-core GEMM via mma.sync (HMMA, bf16x2 split, fp32 accum):
//   C[M,128] = dinv[row] * ( f(A) @ W ),  f(a) = relu(a + bin) if bin.
// 512 threads / CTA; warp = 16 rows x 64 cols of the 128x128 tile.
// ---------------------------------------------------------------------------
__global__ __launch_bounds__(512, 1)
void gemm_mma(const float* __restrict__ A, int wl,
              const float* __restrict__ bin, const float* __restrict__ dinv,
              float* __restrict__ C) {
    extern __shared__ char sm[];
    const int tid  = threadIdx.x;
    const int wid  = tid >> 5;
    const int lane = tid & 31;
    const int bm   = blockIdx.x * MTILE;

    const uint32_t uBase = smem_u32(sm);
    const uint32_t uAhi = uBase;
    const uint32_t uAlo = uBase + TILEB;
    const uint32_t uWhi = uBase + 2 * TILEB;
    const uint32_t uWlo = uBase + 3 * TILEB;

    // ---- Fill W tiles (row r: 16 uint4 = 256 B payload, padded to 272 B) ----
    {
        const uint4* whi = (const uint4*)g_Wt[wl][0];
        const uint4* wlo = (const uint4*)g_Wt[wl][1];
#pragma unroll
        for (int i = tid; i < 2048; i += 512) {
            int r  = i >> 4;
            int c4 = i & 15;
            uint32_t off = (uint32_t)r * (PADH * 2) + c4 * 16;
            *(uint4*)(sm + (uWhi - uBase) + off) = __ldg(&whi[i]);
            *(uint4*)(sm + (uWlo - uBase) + off) = __ldg(&wlo[i]);
        }
    }

    // ---- Load A tile (fp32), fused bias+ReLU, split into bf16 hi/lo ----
#pragma unroll
    for (int idx = tid; idx < MTILE * 32; idx += 512) {
        int r  = idx >> 5;
        int c4 = idx & 31;
        int row = bm + r;
        float4 v = make_float4(0.f, 0.f, 0.f, 0.f);
        if (row < NNODES)
            v = *(const float4*)&A[(size_t)row * 128 + c4 * 4];
        if (bin) {
            float4 bb = *(const float4*)&bin[c4 * 4];
            v.x = fmaxf(v.x + bb.x, 0.f);
            v.y = fmaxf(v.y + bb.y, 0.f);
            v.z = fmaxf(v.z + bb.z, 0.f);
            v.w = fmaxf(v.w + bb.w, 0.f);
        }
        __nv_bfloat16 h0 = __float2bfloat16(v.x), h1 = __float2bfloat16(v.y);
        __nv_bfloat16 h2 = __float2bfloat16(v.z), h3 = __float2bfloat16(v.w);
        __nv_bfloat16 l0 = __float2bfloat16(v.x - __bfloat162float(h0));
        __nv_bfloat16 l1 = __float2bfloat16(v.y - __bfloat162float(h1));
        __nv_bfloat16 l2 = __float2bfloat16(v.z - __bfloat162float(h2));
        __nv_bfloat16 l3 = __float2bfloat16(v.w - __bfloat162float(h3));
        uint32_t off = (uint32_t)r * (PADH * 2) + c4 * 8;
        *(__nv_bfloat162*)(sm + off)              = __halves2bfloat162(h0, h1);
        *(__nv_bfloat162*)(sm + off + 4)          = __halves2bfloat162(h2, h3);
        *(__nv_bfloat162*)(sm + TILEB + off)      = __halves2bfloat162(l0, l1);
        *(__nv_bfloat162*)(sm + TILEB + off + 4)  = __halves2bfloat162(l2, l3);
    }
    __syncthreads();

    // ---- MMA main loop ----
    const int mt = wid >> 1;      // m-tile (16 rows)
    const int nh = wid & 1;       // n-half (64 cols)
    const int lr = lane & 15;
    const int lc = lane >> 4;

    float acc[8][4];
#pragma unroll
    for (int j = 0; j < 8; j++)
#pragma unroll
        for (int q = 0; q < 4; q++) acc[j][q] = 0.0f;

#pragma unroll
    for (int ks = 0; ks < 8; ks++) {
        uint32_t aoff = (uint32_t)(mt * 16 + lr) * (PADH * 2) + (ks * 16 + lc * 8) * 2;
        uint32_t aH[4], aL[4];
        LDSM_X4(aH, uAhi + aoff);
        LDSM_X4(aL, uAlo + aoff);

        uint32_t brow = (uint32_t)(ks * 16 + lr) * (PADH * 2);
        uint32_t bH[4][4], bL[4][4];
#pragma unroll
        for (int p = 0; p < 4; p++) {
            uint32_t boff = brow + (nh * 64 + p * 16 + lc * 8) * 2;
            LDSM_X4T(bH[p], uWhi + boff);
            LDSM_X4T(bL[p], uWlo + boff);
        }
#pragma unroll
        for (int p = 0; p < 4; p++) {
            MMA_BF16(acc[2 * p],     aH, bH[p][0], bH[p][1]);
            MMA_BF16(acc[2 * p + 1], aH, bH[p][2], bH[p][3]);
            MMA_BF16(acc[2 * p],     aL, bH[p][0], bH[p][1]);
            MMA_BF16(acc[2 * p + 1], aL, bH[p][2], bH[p][3]);
            MMA_BF16(acc[2 * p],     aH, bL[p][0], bL[p][1]);
            MMA_BF16(acc[2 * p + 1], aH, bL[p][2], bL[p][3]);
        }
    }

    // ---- Epilogue: dinv scaling, float2 stores ----
    {
        int row0 = bm + mt * 16 + (lane >> 2);
        int row1 = row0 + 8;
        float s0 = (row0 < NNODES) ? __ldg(&dinv[row0]) : 0.f;
        float s1 = (row1 < NNODES) ? __ldg(&dinv[row1]) : 0.f;
        int colb = nh * 64 + (lane & 3) * 2;
        if (row0 < NNODES) {
            float* o = &C[(size_t)row0 * 128 + colb];
#pragma unroll
            for (int j = 0; j < 8; j++)
                *(float2*)(o + j * 8) = make_float2(acc[j][0] * s0, acc[j][1] * s0);
        }
        if (row1 < NNODES) {
            float* o = &C[(size_t)row1 * 128 + colb];
#pragma unroll
            for (int j = 0; j < 8; j++)
                *(float2*)(o + j * 8) = make_float2(acc[j][2] * s1, acc[j][3] * s1);
        }
    }
}

// ---------------------------------------------------------------------------
// Gather: one warp per node d.
//   agg[d,:] = dinv[d] * ( hs[d,:] + sum_{s in in(d)} hs[s,:] )
// ---------------------------------------------------------------------------
__global__ __launch_bounds__(256)
void gather(const float* __restrict__ hs, float* __restrict__ out) {
    int w = (int)((blockIdx.x * (unsigned)blockDim.x + threadIdx.x) >> 5);
    if (w >= NNODES) return;
    int lane = threadIdx.x & 31;
    const float4* hp = (const float4*)hs;

    int e    = g_off[w];
    int eend = g_off[w + 1];

    float4 acc = __ldg(&hp[w * 32 + lane]);

    for (; e + 4 <= eend; e += 4) {
        int s0 = __ldg(&g_csr[e + 0]);
        int s1 = __ldg(&g_csr[e + 1]);
        int s2 = __ldg(&g_csr[e + 2]);
        int s3 = __ldg(&g_csr[e + 3]);
        float4 v0 = __ldg(&hp[s0 * 32 + lane]);
        float4 v1 = __ldg(&hp[s1 * 32 + lane]);
        float4 v2 = __ldg(&hp[s2 * 32 + lane]);
        float4 v3 = __ldg(&hp[s3 * 32 + lane]);
        acc.x += (v0.x + v1.x) + (v2.x + v3.x);
        acc.y += (v0.y + v1.y) + (v2.y + v3.y);
        acc.z += (v0.z + v1.z) + (v2.z + v3.z);
        acc.w += (v0.w + v1.w) + (v2.w + v3.w);
    }
    for (; e < eend; e++) {
        int s = __ldg(&g_csr[e]);
        float4 v = __ldg(&hp[s * 32 + lane]);
        acc.x += v.x; acc.y += v.y; acc.z += v.z; acc.w += v.w;
    }

    float sc = __ldg(&g_dinv[w]);
    acc.x *= sc; acc.y *= sc; acc.z *= sc; acc.w *= sc;
    ((float4*)out)[w * 32 + lane] = acc;
}

// ---------------------------------------------------------------------------
__global__ void bias_relu_out(const float* __restrict__ agg,
                              const float* __restrict__ b,
                              float* __restrict__ out) {
    int idx = blockIdx.x * blockDim.x + threadIdx.x;
    if (idx >= NNODES * 32) return;
    int c4 = idx & 31;
    float4 bb = *(const float4*)&b[c4 * 4];
    float4 v = ((const float4*)agg)[idx];
    v.x = fmaxf(v.x + bb.x, 0.f);
    v.y = fmaxf(v.y + bb.y, 0.f);
    v.z = fmaxf(v.z + bb.z, 0.f);
    v.w = fmaxf(v.w + bb.w, 0.f);
    ((float4*)out)[idx] = v;
}

// ---------------------------------------------------------------------------
extern "C" void kernel_launch(void* const* d_in, const int* in_sizes, int n_in,
                              void* d_out, int out_size) {
    const float* x  = (const float*)d_in[0];
    const int*   ei = (const int*)d_in[1];
    const float* W0 = (const float*)d_in[2];
    const float* b0 = (const float*)d_in[3];
    const float* W1 = (const float*)d_in[4];
    const float* b1 = (const float*)d_in[5];
    const float* W2 = (const float*)d_in[6];
    const float* b2 = (const float*)d_in[7];
    const int* src = ei;
    const int* dst = ei + EEDGES;

    float *h, *agg, *dinv;
    cudaGetSymbolAddress((void**)&h,    g_h);
    cudaGetSymbolAddress((void**)&agg,  g_agg);
    cudaGetSymbolAddress((void**)&dinv, g_dinv);

    cudaFuncSetAttribute(gemm_mma, cudaFuncAttributeMaxDynamicSharedMemorySize, SMEM_DYN);

    // Degree + CSR build
    zero_deg<<<(NNODES + 255) / 256, 256>>>();
    deg_count<<<(EEDGES + 255) / 256, 256>>>(dst);
    dinv_kernel<<<(NNODES + 255) / 256, 256>>>();
    scan1<<<NSCAN, SCAN_T>>>();
    scan2<<<1, 32>>>();
    scan3<<<(NNODES + 255) / 256, 256>>>();
    csr_fill<<<(EEDGES + 255) / 256, 256>>>(src, dst);
    prep_w<<<(3 * 16384 + 255) / 256, 256>>>(W0, W1, W2);

    const float* bs[3] = {b0, b1, b2};

    const float* in = x;
    const int elem_blocks   = (NNODES * 32 + 255) / 256;
    const int gather_blocks = (NNODES + 7) / 8;

    for (int l = 0; l < 3; l++) {
        gemm_mma<<<NTILES, 512, SMEM_DYN>>>(in, l, l ? bs[l - 1] : nullptr, dinv, h);
        gather<<<gather_blocks, 256>>>(h, agg);
        in = agg;
    }

    bias_relu_out<<<elem_blocks, 256>>>(agg, b2, (float*)d_out);
}

// round 5
// speedup vs baseline: 3.5376x; 1.1859x over previous
#include <cuda_runtime.h>
#include <cuda_bf16.h>
#include <cuda_fp16.h>
#include <cstdint>

#define NNODES 100000
#define EEDGES 1600000
#define HDIM   128

#define SCAN_BLK 1024
#define SCAN_T   256
#define NSCAN    ((NNODES + SCAN_BLK - 1) / SCAN_BLK)   // 98

#define MTILE   128
#define NTILES  ((NNODES + MTILE - 1) / MTILE)          // 782
#define PADH    136                                      // halves per padded row (272 B)
#define TILEB   (128 * PADH * 2)                         // 34816 B per bf16 tile
#define SMEM_DYN (4 * TILEB)                             // A_hi, A_lo, W_hi, W_lo

// ---------------------------------------------------------------------------
// Scratch (device globals)
// ---------------------------------------------------------------------------
__device__ __half g_h16[(size_t)NNODES * HDIM];   // 25.6 MB: post-GEMM (dinv-scaled), fp16
__device__ float  g_agg[(size_t)NNODES * HDIM];   // 51.2 MB: aggregated features (fp32)
__device__ float  g_dinv[NNODES];
__device__ int    g_deg[NNODES];
__device__ int    g_off[NNODES + 1];
__device__ int    g_cur[NNODES];
__device__ int    g_csr[EEDGES];
__device__ int    g_bsum[NSCAN];
__device__ int    g_bbase[NSCAN];
__device__ __nv_bfloat16 g_Wt[3][2][128 * 128];   // k-major W, hi/lo split

// ---------------------------------------------------------------------------
__device__ __forceinline__ uint32_t smem_u32(const void* p) {
    uint32_t a;
    asm("{ .reg .u64 t; cvta.to.shared.u64 t, %1; cvt.u32.u64 %0, t; }"
        : "=r"(a) : "l"(p));
    return a;
}

#define LDSM_X4(r, a) \
    asm volatile("ldmatrix.sync.aligned.m8n8.x4.shared.b16 {%0,%1,%2,%3}, [%4];" \
                 : "=r"((r)[0]), "=r"((r)[1]), "=r"((r)[2]), "=r"((r)[3]) : "r"(a))
#define LDSM_X4T(r, a) \
    asm volatile("ldmatrix.sync.aligned.m8n8.x4.trans.shared.b16 {%0,%1,%2,%3}, [%4];" \
                 : "=r"((r)[0]), "=r"((r)[1]), "=r"((r)[2]), "=r"((r)[3]) : "r"(a))
#define MMA_BF16(c, a, b0, b1) \
    asm volatile("mma.sync.aligned.m16n8k16.row.col.f32.bf16.bf16.f32 " \
                 "{%0,%1,%2,%3}, {%4,%5,%6,%7}, {%8,%9}, {%0,%1,%2,%3};" \
                 : "+f"((c)[0]), "+f"((c)[1]), "+f"((c)[2]), "+f"((c)[3]) \
                 : "r"((a)[0]), "r"((a)[1]), "r"((a)[2]), "r"((a)[3]), \
                   "r"(b0), "r"(b1))

// ---------------------------------------------------------------------------
// Degree / CSR build
// ---------------------------------------------------------------------------
__global__ void zero_deg() {
    int i = blockIdx.x * blockDim.x + threadIdx.x;
    if (i < NNODES) g_deg[i] = 0;
}
__global__ void deg_count(const int* __restrict__ dst) {
    int e = blockIdx.x * blockDim.x + threadIdx.x;
    if (e < EEDGES) atomicAdd(&g_deg[dst[e]], 1);
}
__global__ void dinv_kernel() {
    int i = blockIdx.x * blockDim.x + threadIdx.x;
    if (i < NNODES) g_dinv[i] = rsqrtf((float)g_deg[i] + 1.0f);
}
__global__ __launch_bounds__(SCAN_T)
void scan1() {
    __shared__ int sh[SCAN_T];
    int b = blockIdx.x, t = threadIdx.x;
    int base = b * SCAN_BLK + t * 4;
    int v[4];
#pragma unroll
    for (int j = 0; j < 4; j++) {
        int i = base + j;
        v[j] = (i < NNODES) ? g_deg[i] : 0;
    }
    int tot = v[0] + v[1] + v[2] + v[3];
    sh[t] = tot;
    __syncthreads();
    for (int o = 1; o < SCAN_T; o <<= 1) {
        int x = 0;
        if (t >= o) x = sh[t - o];
        __syncthreads();
        if (t >= o) sh[t] += x;
        __syncthreads();
    }
    int run = sh[t] - tot;
#pragma unroll
    for (int j = 0; j < 4; j++) {
        int i = base + j;
        if (i < NNODES) g_off[i] = run;
        run += v[j];
    }
    if (t == SCAN_T - 1) g_bsum[b] = sh[t];
}
__global__ void scan2() {
    if (threadIdx.x == 0 && blockIdx.x == 0) {
        int run = 0;
        for (int i = 0; i < NSCAN; i++) { g_bbase[i] = run; run += g_bsum[i]; }
        g_off[NNODES] = run;
    }
}
__global__ void scan3() {
    int i = blockIdx.x * blockDim.x + threadIdx.x;
    if (i < NNODES) {
        int v = g_off[i] + g_bbase[i / SCAN_BLK];
        g_off[i] = v;
        g_cur[i] = v;
    }
}
__global__ void csr_fill(const int* __restrict__ src, const int* __restrict__ dst) {
    int e = blockIdx.x * blockDim.x + threadIdx.x;
    if (e < EEDGES) {
        int d = dst[e];
        int slot = atomicAdd(&g_cur[d], 1);
        g_csr[slot] = src[e];
    }
}

// ---------------------------------------------------------------------------
// Prep: split W (k-major, [k][n]) into bf16 hi/lo.
// ---------------------------------------------------------------------------
__global__ void prep_w(const float* __restrict__ W0, const float* __restrict__ W1,
                       const float* __restrict__ W2) {
    int idx = blockIdx.x * blockDim.x + threadIdx.x;
    if (idx >= 3 * 16384) return;
    int l = idx >> 14;
    int e = idx & 16383;
    const float* W = (l == 0) ? W0 : (l == 1) ? W1 : W2;
    float v = W[e];
    __nv_bfloat16 hi = __float2bfloat16(v);
    __nv_bfloat16 lo = __float2bfloat16(v - __bfloat162float(hi));
    g_Wt[l][0][e] = hi;
    g_Wt[l][1][e] = lo;
}

// ---------------------------------------------------------------------------
// Tensor-core GEMM via mma.sync (HMMA, bf16x2 split, fp32 accum):
//   h16[row,:] = fp16( dinv[row] * ( f(A) @ W ) ),  f(a) = relu(a + bin) if bin.
// 512 threads / CTA; warp = 16 rows x 64 cols of the 128x128 tile.
// ---------------------------------------------------------------------------
__global__ __launch_bounds__(512, 1)
void gemm_mma(const float* __restrict__ A, int wl,
              const float* __restrict__ bin, const float* __restrict__ dinv,
              __half* __restrict__ C16) {
    extern __shared__ char sm[];
    const int tid  = threadIdx.x;
    const int wid  = tid >> 5;
    const int lane = tid & 31;
    const int bm   = blockIdx.x * MTILE;

    const uint32_t uBase = smem_u32(sm);
    const uint32_t uAhi = uBase;
    const uint32_t uAlo = uBase + TILEB;
    const uint32_t uWhi = uBase + 2 * TILEB;
    const uint32_t uWlo = uBase + 3 * TILEB;

    // ---- Fill W tiles ----
    {
        const uint4* whi = (const uint4*)g_Wt[wl][0];
        const uint4* wlo = (const uint4*)g_Wt[wl][1];
#pragma unroll
        for (int i = tid; i < 2048; i += 512) {
            int r  = i >> 4;
            int c4 = i & 15;
            uint32_t off = (uint32_t)r * (PADH * 2) + c4 * 16;
            *(uint4*)(sm + (uWhi - uBase) + off) = __ldg(&whi[i]);
            *(uint4*)(sm + (uWlo - uBase) + off) = __ldg(&wlo[i]);
        }
    }

    // ---- Load A tile (fp32), fused bias+ReLU, split into bf16 hi/lo ----
#pragma unroll
    for (int idx = tid; idx < MTILE * 32; idx += 512) {
        int r  = idx >> 5;
        int c4 = idx & 31;
        int row = bm + r;
        float4 v = make_float4(0.f, 0.f, 0.f, 0.f);
        if (row < NNODES)
            v = *(const float4*)&A[(size_t)row * 128 + c4 * 4];
        if (bin) {
            float4 bb = *(const float4*)&bin[c4 * 4];
            v.x = fmaxf(v.x + bb.x, 0.f);
            v.y = fmaxf(v.y + bb.y, 0.f);
            v.z = fmaxf(v.z + bb.z, 0.f);
            v.w = fmaxf(v.w + bb.w, 0.f);
        }
        __nv_bfloat16 h0 = __float2bfloat16(v.x), h1 = __float2bfloat16(v.y);
        __nv_bfloat16 h2 = __float2bfloat16(v.z), h3 = __float2bfloat16(v.w);
        __nv_bfloat16 l0 = __float2bfloat16(v.x - __bfloat162float(h0));
        __nv_bfloat16 l1 = __float2bfloat16(v.y - __bfloat162float(h1));
        __nv_bfloat16 l2 = __float2bfloat16(v.z - __bfloat162float(h2));
        __nv_bfloat16 l3 = __float2bfloat16(v.w - __bfloat162float(h3));
        uint32_t off = (uint32_t)r * (PADH * 2) + c4 * 8;
        *(__nv_bfloat162*)(sm + off)              = __halves2bfloat162(h0, h1);
        *(__nv_bfloat162*)(sm + off + 4)          = __halves2bfloat162(h2, h3);
        *(__nv_bfloat162*)(sm + TILEB + off)      = __halves2bfloat162(l0, l1);
        *(__nv_bfloat162*)(sm + TILEB + off + 4)  = __halves2bfloat162(l2, l3);
    }
    __syncthreads();

    // ---- MMA main loop ----
    const int mt = wid >> 1;
    const int nh = wid & 1;
    const int lr = lane & 15;
    const int lc = lane >> 4;

    float acc[8][4];
#pragma unroll
    for (int j = 0; j < 8; j++)
#pragma unroll
        for (int q = 0; q < 4; q++) acc[j][q] = 0.0f;

#pragma unroll
    for (int ks = 0; ks < 8; ks++) {
        uint32_t aoff = (uint32_t)(mt * 16 + lr) * (PADH * 2) + (ks * 16 + lc * 8) * 2;
        uint32_t aH[4], aL[4];
        LDSM_X4(aH, uAhi + aoff);
        LDSM_X4(aL, uAlo + aoff);

        uint32_t brow = (uint32_t)(ks * 16 + lr) * (PADH * 2);
        uint32_t bH[4][4], bL[4][4];
#pragma unroll
        for (int p = 0; p < 4; p++) {
            uint32_t boff = brow + (nh * 64 + p * 16 + lc * 8) * 2;
            LDSM_X4T(bH[p], uWhi + boff);
            LDSM_X4T(bL[p], uWlo + boff);
        }
#pragma unroll
        for (int p = 0; p < 4; p++) {
            MMA_BF16(acc[2 * p],     aH, bH[p][0], bH[p][1]);
            MMA_BF16(acc[2 * p + 1], aH, bH[p][2], bH[p][3]);
            MMA_BF16(acc[2 * p],     aL, bH[p][0], bH[p][1]);
            MMA_BF16(acc[2 * p + 1], aL, bH[p][2], bH[p][3]);
            MMA_BF16(acc[2 * p],     aH, bL[p][0], bL[p][1]);
            MMA_BF16(acc[2 * p + 1], aH, bL[p][2], bL[p][3]);
        }
    }

    // ---- Epilogue: dinv scaling, fp16 stores ----
    {
        int row0 = bm + mt * 16 + (lane >> 2);
        int row1 = row0 + 8;
        float s0 = (row0 < NNODES) ? __ldg(&dinv[row0]) : 0.f;
        float s1 = (row1 < NNODES) ? __ldg(&dinv[row1]) : 0.f;
        int colb = nh * 64 + (lane & 3) * 2;
        if (row0 < NNODES) {
            __half* o = &C16[(size_t)row0 * 128 + colb];
#pragma unroll
            for (int j = 0; j < 8; j++)
                *(__half2*)(o + j * 8) =
                    __floats2half2_rn(acc[j][0] * s0, acc[j][1] * s0);
        }
        if (row1 < NNODES) {
            __half* o = &C16[(size_t)row1 * 128 + colb];
#pragma unroll
            for (int j = 0; j < 8; j++)
                *(__half2*)(o + j * 8) =
                    __floats2half2_rn(acc[j][2] * s1, acc[j][3] * s1);
        }
    }
}

// ---------------------------------------------------------------------------
// Gather: one warp per node d. fp16 payload, fp32 accumulation.
//   t = dinv[d] * ( h16[d,:] + sum_{s in in(d)} h16[s,:] )
//   out = bias ? relu(t + bias) : t
// Each lane owns 4 halves (uint2 load).
// ---------------------------------------------------------------------------
__global__ __launch_bounds__(256)
void gather(const __half* __restrict__ hs, const float* __restrict__ bias,
            float* __restrict__ out) {
    int w = (int)((blockIdx.x * (unsigned)blockDim.x + threadIdx.x) >> 5);
    if (w >= NNODES) return;
    int lane = threadIdx.x & 31;
    const uint2* hp = (const uint2*)hs;   // 32 uint2 per 128-half row

    int e    = g_off[w];
    int eend = g_off[w + 1];

    float4 acc;
    {
        uint2 u = __ldg(&hp[w * 32 + lane]);
        float2 a = __half22float2(*(const __half2*)&u.x);
        float2 b = __half22float2(*(const __half2*)&u.y);
        acc = make_float4(a.x, a.y, b.x, b.y);
    }

    for (; e + 4 <= eend; e += 4) {
        int s0 = __ldg(&g_csr[e + 0]);
        int s1 = __ldg(&g_csr[e + 1]);
        int s2 = __ldg(&g_csr[e + 2]);
        int s3 = __ldg(&g_csr[e + 3]);
        uint2 u0 = __ldg(&hp[s0 * 32 + lane]);
        uint2 u1 = __ldg(&hp[s1 * 32 + lane]);
        uint2 u2 = __ldg(&hp[s2 * 32 + lane]);
        uint2 u3 = __ldg(&hp[s3 * 32 + lane]);
        float2 a0 = __half22float2(*(const __half2*)&u0.x);
        float2 b0 = __half22float2(*(const __half2*)&u0.y);
        float2 a1 = __half22float2(*(const __half2*)&u1.x);
        float2 b1 = __half22float2(*(const __half2*)&u1.y);
        float2 a2 = __half22float2(*(const __half2*)&u2.x);
        float2 b2 = __half22float2(*(const __half2*)&u2.y);
        float2 a3 = __half22float2(*(const __half2*)&u3.x);
        float2 b3 = __half22float2(*(const __half2*)&u3.y);
        acc.x += (a0.x + a1.x) + (a2.x + a3.x);
        acc.y += (a0.y + a1.y) + (a2.y + a3.y);
        acc.z += (b0.x + b1.x) + (b2.x + b3.x);
        acc.w += (b0.y + b1.y) + (b2.y + b3.y);
    }
    for (; e < eend; e++) {
        int s = __ldg(&g_csr[e]);
        uint2 u = __ldg(&hp[s * 32 + lane]);
        float2 a = __half22float2(*(const __half2*)&u.x);
        float2 b = __half22float2(*(const __half2*)&u.y);
        acc.x += a.x; acc.y += a.y; acc.z += b.x; acc.w += b.y;
    }

    float sc = __ldg(&g_dinv[w]);
    acc.x *= sc; acc.y *= sc; acc.z *= sc; acc.w *= sc;

    if (bias) {
        float4 bb = *(const float4*)&bias[lane * 4];
        acc.x = fmaxf(acc.x + bb.x, 0.f);
        acc.y = fmaxf(acc.y + bb.y, 0.f);
        acc.z = fmaxf(acc.z + bb.z, 0.f);
        acc.w = fmaxf(acc.w + bb.w, 0.f);
    }
    ((float4*)out)[w * 32 + lane] = acc;
}

// ---------------------------------------------------------------------------
extern "C" void kernel_launch(void* const* d_in, const int* in_sizes, int n_in,
                              void* d_out, int out_size) {
    const float* x  = (const float*)d_in[0];
    const int*   ei = (const int*)d_in[1];
    const float* W0 = (const float*)d_in[2];
    const float* b0 = (const float*)d_in[3];
    const float* W1 = (const float*)d_in[4];
    const float* b1 = (const float*)d_in[5];
    const float* W2 = (const float*)d_in[6];
    const float* b2 = (const float*)d_in[7];
    const int* src = ei;
    const int* dst = ei + EEDGES;

    __half* h16;
    float *agg, *dinv;
    cudaGetSymbolAddress((void**)&h16,  g_h16);
    cudaGetSymbolAddress((void**)&agg,  g_agg);
    cudaGetSymbolAddress((void**)&dinv, g_dinv);

    cudaFuncSetAttribute(gemm_mma, cudaFuncAttributeMaxDynamicSharedMemorySize, SMEM_DYN);

    // Degree + CSR build
    zero_deg<<<(NNODES + 255) / 256, 256>>>();
    deg_count<<<(EEDGES + 255) / 256, 256>>>(dst);
    dinv_kernel<<<(NNODES + 255) / 256, 256>>>();
    scan1<<<NSCAN, SCAN_T>>>();
    scan2<<<1, 32>>>();
    scan3<<<(NNODES + 255) / 256, 256>>>();
    csr_fill<<<(EEDGES + 255) / 256, 256>>>(src, dst);
    prep_w<<<(3 * 16384 + 255) / 256, 256>>>(W0, W1, W2);

    const float* bs[3] = {b0, b1, b2};

    const float* in = x;
    const int gather_blocks = (NNODES + 7) / 8;

    for (int l = 0; l < 3; l++) {
        gemm_mma<<<NTILES, 512, SMEM_DYN>>>(in, l, l ? bs[l - 1] : nullptr, dinv, h16);
        if (l < 2) {
            gather<<<gather_blocks, 256>>>(h16, nullptr, agg);
            in = agg;
        } else {
            gather<<<gather_blocks, 256>>>(h16, b2, (float*)d_out);
        }
    }
}